// round 14
// baseline (speedup 1.0000x reference)
#include <cuda_runtime.h>

#define N_PTS 64
#define NA 67   // n + 3
#define NC 69   // augmented columns (NA + 2 RHS)

// Solved TPS weights: w[i*2 + c]; rows 0..63 kernel weights, 64..66 affine.
__device__ float g_w[NA * 2];

// ---------------------------------------------------------------------------
// Blocked (lookahead-4) fp32 Gauss-Jordan with implicit partial pivoting.
// 544 threads = 68 rows x 8 col-lanes. 17 barrier-rounds (16x PW=4 + 1x PW=3).
// (R9/R11 configuration: measured ~31 us, rel_err 6.43e-5. UNCHANGED.)
// ---------------------------------------------------------------------------

template<int PW>
__device__ __forceinline__ void gj_round(
    const float (*__restrict__ Mc)[NC], float (*__restrict__ Mn)[NC],
    int k0, int er, int ec, bool row_ok, int lane, int tid,
    unsigned& pm0, unsigned& pm1, unsigned& pm2,
    float* __restrict__ s_inv, int* __restrict__ s_prs)
{
    const int r0 = lane, r1 = lane + 32, r2 = lane + 64;
    const bool r2ok = (r2 < NA);

    float c0[PW], c1[PW], c2[PW], own[PW];
    #pragma unroll
    for (int c = 0; c < PW; c++) {
        c0[c]  = Mc[r0][k0 + c];
        c1[c]  = Mc[r1][k0 + c];
        c2[c]  = r2ok ? Mc[r2][k0 + c] : 0.0f;
        own[c] = Mc[row_ok ? er : 0][k0 + c];
    }

    float fh0[PW], fh1[PW], fh2[PW];
    float fown[PW];
    int   prs[PW];
    float fp[PW][PW];

    #pragma unroll
    for (int t = 0; t < PW; t++) {
        unsigned key = 0;
        {
            unsigned b = (__float_as_uint(c0[t]) & 0x7FFFFF80u) | (unsigned)r0;
            if (!((pm0 >> lane) & 1u)) key = b;
        }
        {
            unsigned b = (__float_as_uint(c1[t]) & 0x7FFFFF80u) | (unsigned)r1;
            if (!((pm1 >> lane) & 1u) && b > key) key = b;
        }
        if (r2ok) {
            unsigned b = (__float_as_uint(c2[t]) & 0x7FFFFF80u) | (unsigned)r2;
            if (!((pm2 >> lane) & 1u) && b > key) key = b;
        }
        key = __reduce_max_sync(0xFFFFFFFFu, key);
        const int pr = (int)(key & 0x7Fu);
        prs[t] = pr;
        if (pr < 32)      pm0 |= 1u << pr;
        else if (pr < 64) pm1 |= 1u << (pr - 32);
        else              pm2 |= 1u << (pr - 64);

        const int slot = pr >> 5;
        const int pl   = pr & 31;

        float pivc = (slot == 0) ? c0[t] : ((slot == 1) ? c1[t] : c2[t]);
        const float piv = __shfl_sync(0xFFFFFFFFu, pivc, pl);
        const float inv = __fdividef(1.0f, piv);
        if (tid == 0) { s_inv[k0 + t] = inv; s_prs[k0 + t] = pr; }

        float urow[PW];
        #pragma unroll
        for (int c = t + 1; c < PW; c++) {
            float uc = (slot == 0) ? c0[c] : ((slot == 1) ? c1[c] : c2[c]);
            urow[c] = __shfl_sync(0xFFFFFFFFu, uc, pl);
        }
        #pragma unroll
        for (int s = 0; s < t; s++) {
            float fhv = (slot == 0) ? fh0[s] : ((slot == 1) ? fh1[s] : fh2[s]);
            fp[t][s] = __shfl_sync(0xFFFFFFFFu, fhv, pl);
        }

        float f0 = (r0 == pr)          ? 0.0f : c0[t] * inv;
        float f1 = (r1 == pr)          ? 0.0f : c1[t] * inv;
        float f2 = (!r2ok || r2 == pr) ? 0.0f : c2[t] * inv;
        float fo = (!row_ok || er == pr) ? 0.0f : own[t] * inv;
        fh0[t] = f0; fh1[t] = f1; fh2[t] = f2; fown[t] = fo;

        #pragma unroll
        for (int c = t + 1; c < PW; c++) {
            c0[c]  = fmaf(-f0, urow[c], c0[c]);
            c1[c]  = fmaf(-f1, urow[c], c1[c]);
            c2[c]  = fmaf(-f2, urow[c], c2[c]);
            own[c] = fmaf(-fo, urow[c], own[c]);
        }
    }

    if (row_ok) {
        for (int j = k0 + PW + ec; j < NC; j += 8) {
            float u[PW];
            #pragma unroll
            for (int t = 0; t < PW; t++) {
                float v = Mc[prs[t]][j];
                #pragma unroll
                for (int s = 0; s < t; s++) v = fmaf(-fp[t][s], u[s], v);
                u[t] = v;
            }
            float nv = Mc[er][j];
            #pragma unroll
            for (int t = 0; t < PW; t++) nv = fmaf(-fown[t], u[t], nv);
            Mn[er][j] = nv;
        }
    }
}

__global__ void __launch_bounds__(544) tps_solve_kernel(
    const float* __restrict__ pts, const float* __restrict__ vals)
{
    __shared__ float M[2][NA][NC];
    __shared__ float s_inv[NA];
    __shared__ int   s_prs[NA];

    const int tid  = threadIdx.x;
    const int nt   = blockDim.x;
    const int lane = tid & 31;

    for (int idx = tid; idx < NA * NC; idx += nt) {
        int i = idx / NC, j = idx % NC;
        float v = 0.0f;
        if (i < N_PTS) {
            if (j < N_PTS) {
                float dx = pts[2*i]   - pts[2*j];
                float dy = pts[2*i+1] - pts[2*j+1];
                v = sqrtf(fmaf(dx, dx, dy*dy));
            } else if (j < NA) {
                int k = j - N_PTS;
                v = (k == 0) ? 1.0f : pts[2*i + (k-1)];
            } else {
                v = vals[2*i + (j - NA)];
            }
        } else if (j < N_PTS) {
            int k = i - N_PTS;
            v = (k == 0) ? 1.0f : pts[2*j + (k-1)];
        }
        M[0][i][j] = v;
    }
    __syncthreads();

    const int er = tid >> 3;
    const int ec = tid & 7;
    const bool row_ok = (er < NA);
    unsigned pm0 = 0, pm1 = 0, pm2 = 0;

    int cur = 0;
    #pragma unroll 1
    for (int r = 0; r < 16; r++) {
        gj_round<4>(M[cur], M[cur ^ 1], r * 4, er, ec, row_ok, lane, tid,
                    pm0, pm1, pm2, s_inv, s_prs);
        __syncthreads();
        cur ^= 1;
    }
    gj_round<3>(M[cur], M[cur ^ 1], 64, er, ec, row_ok, lane, tid,
                pm0, pm1, pm2, s_inv, s_prs);
    __syncthreads();
    cur ^= 1;

    if (tid < NA) {
        int pr = s_prs[tid];
        float inv = s_inv[tid];
        g_w[tid*2]   = M[cur][pr][NA]   * inv;
        g_w[tid*2+1] = M[cur][pr][NA+1] * inv;
    }
}

// ---------------------------------------------------------------------------
// Kernel 2: dense evaluation, 8 x-adjacent pixels per thread.
// (a) single float4 {px,py,w0,w1} LDS.128 per point,
// (b) i-loop unroll 4 (body ~2.9KB -> fits L0 I-cache).
// ---------------------------------------------------------------------------
__device__ __forceinline__ float fsqrt_approx(float x) {
    float r;
    asm("sqrt.approx.f32 %0, %1;" : "=f"(r) : "f"(x));
    return r;
}
__device__ __forceinline__ unsigned long long pack2(float lo, float hi) {
    unsigned long long r;
    asm("mov.b64 %0, {%1, %2};" : "=l"(r) : "f"(lo), "f"(hi));
    return r;
}
__device__ __forceinline__ void unpack2(unsigned long long v, float& lo, float& hi) {
    asm("mov.b64 {%0, %1}, %2;" : "=f"(lo), "=f"(hi) : "l"(v));
}

__global__ void __launch_bounds__(128) tps_eval_kernel(
    const float* __restrict__ pts, float* __restrict__ out)
{
    __shared__ float4 cpw[N_PTS];   // {px, py, w0, w1}
    __shared__ float  aff[6];
    const int tid = threadIdx.x;

    if (tid < N_PTS) {
        cpw[tid] = make_float4(pts[2*tid], pts[2*tid+1],
                               g_w[2*tid], g_w[2*tid+1]);
    }
    if (tid < 6) aff[tid] = g_w[2*N_PTS + tid];
    __syncthreads();

    const int gid = blockIdx.x * blockDim.x + tid;   // 0 .. 131071
    const int x0  = (gid & 127) << 3;
    const int y   = gid >> 7;

    const float fy = (float)y;
    float fx[8];
    #pragma unroll
    for (int j = 0; j < 8; j++) fx[j] = (float)(x0 + j);

    unsigned long long acc[8];
    #pragma unroll
    for (int j = 0; j < 8; j++) {
        float a0 = fmaf(aff[2], fx[j], fmaf(aff[4], fy, aff[0]));
        float a1 = fmaf(aff[3], fx[j], fmaf(aff[5], fy, aff[1]));
        acc[j] = pack2(a0, a1);
    }

    #pragma unroll 4
    for (int i = 0; i < N_PTS; i++) {
        float4 c = cpw[i];                      // one LDS.128
        unsigned long long wv = pack2(c.z, c.w);
        float dy  = fy - c.y;
        float dy2 = dy * dy;
        #pragma unroll
        for (int j = 0; j < 8; j++) {
            float dx = fx[j] - c.x;
            float d2 = fmaf(dx, dx, dy2);
            float d  = fsqrt_approx(d2);
            unsigned long long dd = pack2(d, d);
            asm("fma.rn.f32x2 %0, %1, %2, %0;" : "+l"(acc[j]) : "l"(dd), "l"(wv));
        }
    }

    // 8 px * 2 ch = 16 consecutive floats = 4 float4 at outv[gid*4 .. +3]
    float4* outv = reinterpret_cast<float4*>(out);
    #pragma unroll
    for (int q = 0; q < 4; q++) {
        float4 o;
        unpack2(acc[q*2],     o.x, o.y);
        unpack2(acc[q*2 + 1], o.z, o.w);
        outv[gid*4 + q] = o;
    }
}

// ---------------------------------------------------------------------------
extern "C" void kernel_launch(void* const* d_in, const int* in_sizes, int n_in,
                              void* d_out, int out_size)
{
    const float* pts  = (const float*)d_in[0];
    const float* vals = (const float*)d_in[1];
    float* out = (float*)d_out;

    tps_solve_kernel<<<1, 544>>>(pts, vals);
    tps_eval_kernel<<<1024, 128>>>(pts, out);
}

// round 15
// speedup vs baseline: 1.0445x; 1.0445x over previous
#include <cuda_runtime.h>

#define N_PTS 64
#define NA 67   // n + 3
#define NC 69   // augmented columns (NA + 2 RHS)

// Solved TPS weights: w[i*2 + c]; rows 0..63 kernel weights, 64..66 affine.
__device__ float g_w[NA * 2];

// ---------------------------------------------------------------------------
// Blocked (lookahead-4) fp32 Gauss-Jordan with implicit partial pivoting.
// 544 threads = 68 rows x 8 col-lanes. 17 barrier-rounds (16x PW=4 + 1x PW=3).
// (R9/R11 configuration: measured ~31 us, rel_err 6.43e-5. UNCHANGED.)
// ---------------------------------------------------------------------------

template<int PW>
__device__ __forceinline__ void gj_round(
    const float (*__restrict__ Mc)[NC], float (*__restrict__ Mn)[NC],
    int k0, int er, int ec, bool row_ok, int lane, int tid,
    unsigned& pm0, unsigned& pm1, unsigned& pm2,
    float* __restrict__ s_inv, int* __restrict__ s_prs)
{
    const int r0 = lane, r1 = lane + 32, r2 = lane + 64;
    const bool r2ok = (r2 < NA);

    float c0[PW], c1[PW], c2[PW], own[PW];
    #pragma unroll
    for (int c = 0; c < PW; c++) {
        c0[c]  = Mc[r0][k0 + c];
        c1[c]  = Mc[r1][k0 + c];
        c2[c]  = r2ok ? Mc[r2][k0 + c] : 0.0f;
        own[c] = Mc[row_ok ? er : 0][k0 + c];
    }

    float fh0[PW], fh1[PW], fh2[PW];
    float fown[PW];
    int   prs[PW];
    float fp[PW][PW];

    #pragma unroll
    for (int t = 0; t < PW; t++) {
        unsigned key = 0;
        {
            unsigned b = (__float_as_uint(c0[t]) & 0x7FFFFF80u) | (unsigned)r0;
            if (!((pm0 >> lane) & 1u)) key = b;
        }
        {
            unsigned b = (__float_as_uint(c1[t]) & 0x7FFFFF80u) | (unsigned)r1;
            if (!((pm1 >> lane) & 1u) && b > key) key = b;
        }
        if (r2ok) {
            unsigned b = (__float_as_uint(c2[t]) & 0x7FFFFF80u) | (unsigned)r2;
            if (!((pm2 >> lane) & 1u) && b > key) key = b;
        }
        key = __reduce_max_sync(0xFFFFFFFFu, key);
        const int pr = (int)(key & 0x7Fu);
        prs[t] = pr;
        if (pr < 32)      pm0 |= 1u << pr;
        else if (pr < 64) pm1 |= 1u << (pr - 32);
        else              pm2 |= 1u << (pr - 64);

        const int slot = pr >> 5;
        const int pl   = pr & 31;

        float pivc = (slot == 0) ? c0[t] : ((slot == 1) ? c1[t] : c2[t]);
        const float piv = __shfl_sync(0xFFFFFFFFu, pivc, pl);
        const float inv = __fdividef(1.0f, piv);
        if (tid == 0) { s_inv[k0 + t] = inv; s_prs[k0 + t] = pr; }

        float urow[PW];
        #pragma unroll
        for (int c = t + 1; c < PW; c++) {
            float uc = (slot == 0) ? c0[c] : ((slot == 1) ? c1[c] : c2[c]);
            urow[c] = __shfl_sync(0xFFFFFFFFu, uc, pl);
        }
        #pragma unroll
        for (int s = 0; s < t; s++) {
            float fhv = (slot == 0) ? fh0[s] : ((slot == 1) ? fh1[s] : fh2[s]);
            fp[t][s] = __shfl_sync(0xFFFFFFFFu, fhv, pl);
        }

        float f0 = (r0 == pr)          ? 0.0f : c0[t] * inv;
        float f1 = (r1 == pr)          ? 0.0f : c1[t] * inv;
        float f2 = (!r2ok || r2 == pr) ? 0.0f : c2[t] * inv;
        float fo = (!row_ok || er == pr) ? 0.0f : own[t] * inv;
        fh0[t] = f0; fh1[t] = f1; fh2[t] = f2; fown[t] = fo;

        #pragma unroll
        for (int c = t + 1; c < PW; c++) {
            c0[c]  = fmaf(-f0, urow[c], c0[c]);
            c1[c]  = fmaf(-f1, urow[c], c1[c]);
            c2[c]  = fmaf(-f2, urow[c], c2[c]);
            own[c] = fmaf(-fo, urow[c], own[c]);
        }
    }

    if (row_ok) {
        for (int j = k0 + PW + ec; j < NC; j += 8) {
            float u[PW];
            #pragma unroll
            for (int t = 0; t < PW; t++) {
                float v = Mc[prs[t]][j];
                #pragma unroll
                for (int s = 0; s < t; s++) v = fmaf(-fp[t][s], u[s], v);
                u[t] = v;
            }
            float nv = Mc[er][j];
            #pragma unroll
            for (int t = 0; t < PW; t++) nv = fmaf(-fown[t], u[t], nv);
            Mn[er][j] = nv;
        }
    }
}

__global__ void __launch_bounds__(544) tps_solve_kernel(
    const float* __restrict__ pts, const float* __restrict__ vals)
{
    __shared__ float M[2][NA][NC];
    __shared__ float s_inv[NA];
    __shared__ int   s_prs[NA];

    const int tid  = threadIdx.x;
    const int nt   = blockDim.x;
    const int lane = tid & 31;

    for (int idx = tid; idx < NA * NC; idx += nt) {
        int i = idx / NC, j = idx % NC;
        float v = 0.0f;
        if (i < N_PTS) {
            if (j < N_PTS) {
                float dx = pts[2*i]   - pts[2*j];
                float dy = pts[2*i+1] - pts[2*j+1];
                v = sqrtf(fmaf(dx, dx, dy*dy));
            } else if (j < NA) {
                int k = j - N_PTS;
                v = (k == 0) ? 1.0f : pts[2*i + (k-1)];
            } else {
                v = vals[2*i + (j - NA)];
            }
        } else if (j < N_PTS) {
            int k = i - N_PTS;
            v = (k == 0) ? 1.0f : pts[2*j + (k-1)];
        }
        M[0][i][j] = v;
    }
    __syncthreads();

    const int er = tid >> 3;
    const int ec = tid & 7;
    const bool row_ok = (er < NA);
    unsigned pm0 = 0, pm1 = 0, pm2 = 0;

    int cur = 0;
    #pragma unroll 1
    for (int r = 0; r < 16; r++) {
        gj_round<4>(M[cur], M[cur ^ 1], r * 4, er, ec, row_ok, lane, tid,
                    pm0, pm1, pm2, s_inv, s_prs);
        __syncthreads();
        cur ^= 1;
    }
    gj_round<3>(M[cur], M[cur ^ 1], 64, er, ec, row_ok, lane, tid,
                pm0, pm1, pm2, s_inv, s_prs);
    __syncthreads();
    cur ^= 1;

    if (tid < NA) {
        int pr = s_prs[tid];
        float inv = s_inv[tid];
        g_w[tid*2]   = M[cur][pr][NA]   * inv;
        g_w[tid*2+1] = M[cur][pr][NA+1] * inv;
    }
}

// ---------------------------------------------------------------------------
// Kernel 2: dense evaluation, 8 x-adjacent pixels per thread, unroll 8
// (R10 structure), with the distance math on PACKED pixel pairs:
//   dx2  = add.rn.f32x2(fxp, (-px,-px))
//   d2p  = fma.rn.f32x2(dx2, dx2, (dy2,dy2))
// then scalar sqrt.approx per pixel and packed 2-channel accumulate.
// Identical rounding to the scalar path -> identical output.
// ---------------------------------------------------------------------------
__device__ __forceinline__ float fsqrt_approx(float x) {
    float r;
    asm("sqrt.approx.f32 %0, %1;" : "=f"(r) : "f"(x));
    return r;
}
__device__ __forceinline__ unsigned long long pack2(float lo, float hi) {
    unsigned long long r;
    asm("mov.b64 %0, {%1, %2};" : "=l"(r) : "f"(lo), "f"(hi));
    return r;
}
__device__ __forceinline__ void unpack2(unsigned long long v, float& lo, float& hi) {
    asm("mov.b64 {%0, %1}, %2;" : "=f"(lo), "=f"(hi) : "l"(v));
}

__global__ void __launch_bounds__(128) tps_eval_kernel(
    const float* __restrict__ pts, float* __restrict__ out)
{
    __shared__ float2             sp[N_PTS];   // control point (px, py)
    __shared__ unsigned long long sw[N_PTS];   // packed (w0, w1)
    __shared__ float              aff[6];
    const int tid = threadIdx.x;

    if (tid < N_PTS) {
        sp[tid] = make_float2(pts[2*tid], pts[2*tid+1]);
        sw[tid] = pack2(g_w[2*tid], g_w[2*tid+1]);
    }
    if (tid < 6) aff[tid] = g_w[2*N_PTS + tid];
    __syncthreads();

    const int gid = blockIdx.x * blockDim.x + tid;   // 0 .. 131071
    const int x0  = (gid & 127) << 3;
    const int y   = gid >> 7;

    const float fy = (float)y;
    float fx[8];
    #pragma unroll
    for (int j = 0; j < 8; j++) fx[j] = (float)(x0 + j);

    // packed pixel-pair x coordinates
    unsigned long long fxp[4];
    #pragma unroll
    for (int q = 0; q < 4; q++) fxp[q] = pack2(fx[q*2], fx[q*2+1]);

    unsigned long long acc[8];
    #pragma unroll
    for (int j = 0; j < 8; j++) {
        float a0 = fmaf(aff[2], fx[j], fmaf(aff[4], fy, aff[0]));
        float a1 = fmaf(aff[3], fx[j], fmaf(aff[5], fy, aff[1]));
        acc[j] = pack2(a0, a1);
    }

    #pragma unroll 8
    for (int i = 0; i < N_PTS; i++) {
        float2 p = sp[i];
        unsigned long long wv = sw[i];
        float dy  = fy - p.y;
        float dy2 = dy * dy;
        const unsigned long long dy2p = pack2(dy2, dy2);
        const float npx = -p.x;
        const unsigned long long npxp = pack2(npx, npx);
        #pragma unroll
        for (int q = 0; q < 4; q++) {
            unsigned long long dx2, d2p;
            asm("add.rn.f32x2 %0, %1, %2;" : "=l"(dx2) : "l"(fxp[q]), "l"(npxp));
            asm("fma.rn.f32x2 %0, %1, %1, %2;" : "=l"(d2p) : "l"(dx2), "l"(dy2p));
            float d2lo, d2hi;
            unpack2(d2p, d2lo, d2hi);
            float dlo = fsqrt_approx(d2lo);
            float dhi = fsqrt_approx(d2hi);
            unsigned long long ddlo = pack2(dlo, dlo);
            unsigned long long ddhi = pack2(dhi, dhi);
            asm("fma.rn.f32x2 %0, %1, %2, %0;" : "+l"(acc[q*2])   : "l"(ddlo), "l"(wv));
            asm("fma.rn.f32x2 %0, %1, %2, %0;" : "+l"(acc[q*2+1]) : "l"(ddhi), "l"(wv));
        }
    }

    // 8 px * 2 ch = 16 consecutive floats = 4 float4 at outv[gid*4 .. +3]
    float4* outv = reinterpret_cast<float4*>(out);
    #pragma unroll
    for (int q = 0; q < 4; q++) {
        float4 o;
        unpack2(acc[q*2],     o.x, o.y);
        unpack2(acc[q*2 + 1], o.z, o.w);
        outv[gid*4 + q] = o;
    }
}

// ---------------------------------------------------------------------------
extern "C" void kernel_launch(void* const* d_in, const int* in_sizes, int n_in,
                              void* d_out, int out_size)
{
    const float* pts  = (const float*)d_in[0];
    const float* vals = (const float*)d_in[1];
    float* out = (float*)d_out;

    tps_solve_kernel<<<1, 544>>>(pts, vals);
    tps_eval_kernel<<<1024, 128>>>(pts, out);
}